// round 1
// baseline (speedup 1.0000x reference)
#include <cuda_runtime.h>

#define BATCH 4
#define SEQ   8192
#define DIM   512
#define M_TOTAL (BATCH*SEQ)   // 32768

#define NCHUNK 32
#define CHUNK  (SEQ/NCHUNK)   // 256

// ---------------- scratch (device globals; no allocation allowed) ----------
__device__ float g_f[(size_t)M_TOTAL*DIM];   // forget gate, 64MB
__device__ float g_v[(size_t)M_TOTAL*DIM];   // i*g value,   64MB
__device__ float g_P[BATCH*DIM*NCHUNK];
__device__ float g_V[BATCH*DIM*NCHUNK];
__device__ float g_hin[BATCH*DIM*NCHUNK];

__device__ __forceinline__ unsigned f2tf(float x) {
    unsigned u;
    asm("cvt.rna.tf32.f32 %0, %1;" : "=r"(u) : "f"(x));
    return u;
}
__device__ __forceinline__ float sigmoidf_(float x) {
    return 1.0f / (1.0f + __expf(-x));
}

// ---------------- fused GEMM (tf32 mma.sync) + activation epilogue ---------
// Computes Yf = x@Wf+bf, Yi = x@Wi+bi, Yh = x@Wh+bh for a 128x64 output tile
// of each weight simultaneously (x tile read once), then writes
//   g_f = sigmoid(Yf),  g_v = sigmoid(Yi) * g(Yh)
// with g(z) = z>=0 ? z+0.5 : sigmoid(z)   [== exp(log_g(z))]

#define BM 128
#define BN 64
#define BK 16
#define APAD 4   // As[128][20]: conflict-free for the A-fragment access pattern
#define BPAD 8   // Bs[16][72]:  conflict-free for the B-fragment access pattern

__global__ __launch_bounds__(256) void gemm_act(
    const float* __restrict__ x,
    const float* __restrict__ Wf, const float* __restrict__ bf,
    const float* __restrict__ Wi, const float* __restrict__ bi,
    const float* __restrict__ Wh, const float* __restrict__ bh)
{
    __shared__ float As[BM][BK + APAD];
    __shared__ float Bs[3][BK][BN + BPAD];

    const int tid  = threadIdx.x;
    const int lane = tid & 31;
    const int wid  = tid >> 5;
    const int wm   = wid >> 1;   // 0..3  (warp row)
    const int wn   = wid & 1;    // 0..1  (warp col)
    const int m0   = blockIdx.x * BM;
    const int n0   = blockIdx.y * BN;

    const float* Ws[3] = {Wf, Wi, Wh};

    float acc[3][2][4][4];
    #pragma unroll
    for (int w = 0; w < 3; w++)
        #pragma unroll
        for (int mf = 0; mf < 2; mf++)
            #pragma unroll
            for (int nf = 0; nf < 4; nf++)
                #pragma unroll
                for (int r = 0; r < 4; r++)
                    acc[w][mf][nf][r] = 0.0f;

    for (int k0 = 0; k0 < DIM; k0 += BK) {
        // ---- load A tile: 128 x 16 floats = 512 float4, 2 per thread ----
        #pragma unroll
        for (int it = 0; it < 2; it++) {
            int j  = tid + it * 256;
            int r  = j >> 2;
            int cv = j & 3;
            float4 t4 = *(const float4*)(x + (size_t)(m0 + r) * DIM + k0 + cv * 4);
            float4 s4;
            s4.x = __uint_as_float(f2tf(t4.x));
            s4.y = __uint_as_float(f2tf(t4.y));
            s4.z = __uint_as_float(f2tf(t4.z));
            s4.w = __uint_as_float(f2tf(t4.w));
            *(float4*)&As[r][cv * 4] = s4;
        }
        // ---- load B tiles: 3 x (16 x 64) floats, 1 float4/thread/weight ----
        {
            int r  = tid >> 4;
            int cv = tid & 15;
            #pragma unroll
            for (int w = 0; w < 3; w++) {
                float4 t4 = *(const float4*)(Ws[w] + (size_t)(k0 + r) * DIM + n0 + cv * 4);
                float4 s4;
                s4.x = __uint_as_float(f2tf(t4.x));
                s4.y = __uint_as_float(f2tf(t4.y));
                s4.z = __uint_as_float(f2tf(t4.z));
                s4.w = __uint_as_float(f2tf(t4.w));
                *(float4*)&Bs[w][r][cv * 4] = s4;
            }
        }
        __syncthreads();

        #pragma unroll
        for (int kk = 0; kk < BK; kk += 8) {
            unsigned a[2][4];
            #pragma unroll
            for (int mf = 0; mf < 2; mf++) {
                int r = wm * 32 + mf * 16 + (lane >> 2);
                int c = kk + (lane & 3);
                a[mf][0] = __float_as_uint(As[r][c]);
                a[mf][1] = __float_as_uint(As[r + 8][c]);
                a[mf][2] = __float_as_uint(As[r][c + 4]);
                a[mf][3] = __float_as_uint(As[r + 8][c + 4]);
            }
            #pragma unroll
            for (int w = 0; w < 3; w++) {
                #pragma unroll
                for (int nf = 0; nf < 4; nf++) {
                    int cn = wn * 32 + nf * 8 + (lane >> 2);
                    unsigned b0 = __float_as_uint(Bs[w][kk + (lane & 3)][cn]);
                    unsigned b1 = __float_as_uint(Bs[w][kk + (lane & 3) + 4][cn]);
                    #pragma unroll
                    for (int mf = 0; mf < 2; mf++) {
                        float* c = acc[w][mf][nf];
                        asm volatile(
                            "mma.sync.aligned.m16n8k8.row.col.f32.tf32.tf32.f32 "
                            "{%0,%1,%2,%3}, {%4,%5,%6,%7}, {%8,%9}, {%0,%1,%2,%3};"
                            : "+f"(c[0]), "+f"(c[1]), "+f"(c[2]), "+f"(c[3])
                            : "r"(a[mf][0]), "r"(a[mf][1]), "r"(a[mf][2]), "r"(a[mf][3]),
                              "r"(b0), "r"(b1));
                    }
                }
            }
        }
        __syncthreads();
    }

    // ---- epilogue: activations, write f and v ----
    #pragma unroll
    for (int mf = 0; mf < 2; mf++) {
        #pragma unroll
        for (int nf = 0; nf < 4; nf++) {
            int gm0 = m0 + wm * 32 + mf * 16 + (lane >> 2);
            int gn  = n0 + wn * 32 + nf * 8 + 2 * (lane & 3);
            float bf0 = bf[gn], bf1 = bf[gn + 1];
            float bi0 = bi[gn], bi1 = bi[gn + 1];
            float bh0 = bh[gn], bh1 = bh[gn + 1];
            #pragma unroll
            for (int half = 0; half < 2; half++) {
                int gm = gm0 + half * 8;
                float yf0 = acc[0][mf][nf][half * 2 + 0] + bf0;
                float yf1 = acc[0][mf][nf][half * 2 + 1] + bf1;
                float yi0 = acc[1][mf][nf][half * 2 + 0] + bi0;
                float yi1 = acc[1][mf][nf][half * 2 + 1] + bi1;
                float yh0 = acc[2][mf][nf][half * 2 + 0] + bh0;
                float yh1 = acc[2][mf][nf][half * 2 + 1] + bh1;

                float f0 = sigmoidf_(yf0);
                float f1 = sigmoidf_(yf1);
                float gg0 = (yh0 >= 0.0f) ? (yh0 + 0.5f) : sigmoidf_(yh0);
                float gg1 = (yh1 >= 0.0f) ? (yh1 + 0.5f) : sigmoidf_(yh1);
                float v0 = sigmoidf_(yi0) * gg0;
                float v1 = sigmoidf_(yi1) * gg1;

                *(float2*)&g_f[(size_t)gm * DIM + gn] = make_float2(f0, f1);
                *(float2*)&g_v[(size_t)gm * DIM + gn] = make_float2(v0, v1);
            }
        }
    }
}

// ---------------- scan phase 1: per-chunk reduction (P = prod f, V) --------
__global__ __launch_bounds__(DIM) void chunk_reduce()
{
    int c = blockIdx.x;          // chunk
    int b = blockIdx.y;          // batch
    int d = threadIdx.x;         // channel
    size_t base = ((size_t)(b * SEQ + c * CHUNK)) * DIM + d;
    float P = 1.0f, V = 0.0f;
    #pragma unroll 8
    for (int t = 0; t < CHUNK; t++) {
        float f = g_f[base + (size_t)t * DIM];
        float v = g_v[base + (size_t)t * DIM];
        V = fmaf(f, V, v);
        P *= f;
    }
    int ch = b * DIM + d;
    g_P[ch * NCHUNK + c] = P;
    g_V[ch * NCHUNK + c] = V;
}

// ---------------- scan phase 2: sequential carry scan over chunks ----------
__global__ void carry_scan(const float* __restrict__ pre_h)
{
    int ch = blockIdx.x * blockDim.x + threadIdx.x;   // 0..2047
    if (ch >= BATCH * DIM) return;
    int b = ch / DIM, d = ch % DIM;
    float p = pre_h[b * DIM + d];
    float h = (p >= 0.0f) ? (p + 0.5f) : sigmoidf_(p);   // g(pre_h)
    #pragma unroll
    for (int c = 0; c < NCHUNK; c++) {
        g_hin[ch * NCHUNK + c] = h;
        h = fmaf(g_P[ch * NCHUNK + c], h, g_V[ch * NCHUNK + c]);
    }
}

// ---------------- scan phase 3: apply with true carry-in, write output -----
__global__ __launch_bounds__(DIM) void chunk_apply(float* __restrict__ out)
{
    int c = blockIdx.x;
    int b = blockIdx.y;
    int d = threadIdx.x;
    int ch = b * DIM + d;
    float h = g_hin[ch * NCHUNK + c];
    size_t base = ((size_t)(b * SEQ + c * CHUNK)) * DIM + d;
    #pragma unroll 8
    for (int t = 0; t < CHUNK; t++) {
        float f = g_f[base + (size_t)t * DIM];
        float v = g_v[base + (size_t)t * DIM];
        h = fmaf(f, h, v);
        out[base + (size_t)t * DIM] = h;
    }
}

// ---------------- launch ----------------------------------------------------
extern "C" void kernel_launch(void* const* d_in, const int* in_sizes, int n_in,
                              void* d_out, int out_size)
{
    const float* x     = (const float*)d_in[0];
    const float* pre_h = (const float*)d_in[1];
    const float* Wf    = (const float*)d_in[2];
    const float* bf    = (const float*)d_in[3];
    const float* Wi    = (const float*)d_in[4];
    const float* bi    = (const float*)d_in[5];
    const float* Wh    = (const float*)d_in[6];
    const float* bh    = (const float*)d_in[7];
    float* out = (float*)d_out;

    dim3 g1(M_TOTAL / BM, DIM / BN);      // 256 x 8
    gemm_act<<<g1, 256>>>(x, Wf, bf, Wi, bi, Wh, bh);
    chunk_reduce<<<dim3(NCHUNK, BATCH), DIM>>>();
    carry_scan<<<8, 256>>>(pre_h);
    chunk_apply<<<dim3(NCHUNK, BATCH), DIM>>>(out);
}

// round 3
// speedup vs baseline: 1.1618x; 1.1618x over previous
#include <cuda_runtime.h>
#include <cuda_fp16.h>

#define BATCH 4
#define SEQ   8192
#define DIM   512
#define M_TOTAL (BATCH*SEQ)   // 32768

#define NCHUNK 64
#define CHUNK  (SEQ/NCHUNK)   // 128

// ---------------- scratch (device globals; no allocation allowed) ----------
__device__ __half g_f16[(size_t)M_TOTAL*DIM];   // forget gate, 32MB
__device__ __half g_v16[(size_t)M_TOTAL*DIM];   // i*g value,   32MB
__device__ float  g_wc[3*DIM*DIM];              // tf32-converted weights, 3MB
__device__ float  g_P[BATCH*DIM*NCHUNK];
__device__ float  g_V[BATCH*DIM*NCHUNK];
__device__ float  g_hin[BATCH*DIM*NCHUNK];

__device__ __forceinline__ unsigned f2tf(float x) {
    unsigned u;
    asm("cvt.rna.tf32.f32 %0, %1;" : "=r"(u) : "f"(x));
    return u;
}
__device__ __forceinline__ float sigmoidf_(float x) {
    return 1.0f / (1.0f + __expf(-x));
}
__device__ __forceinline__ void cpasync16(unsigned dst, const void* src) {
    asm volatile("cp.async.cg.shared.global [%0], [%1], 16;" :: "r"(dst), "l"(src));
}

// ---------------- prepass: convert weights to tf32 (RNA) -------------------
__global__ __launch_bounds__(256) void wconv(
    const float* __restrict__ Wf, const float* __restrict__ Wi,
    const float* __restrict__ Wh)
{
    int i = blockIdx.x * blockDim.x + threadIdx.x;     // float4 index, 3*65536 total
    const float* src = (i < 65536) ? Wf : (i < 131072) ? Wi : Wh;
    int w = i >> 16;
    int j = (i & 65535) << 2;
    float4 t = *(const float4*)(src + j);
    float4 s;
    s.x = __uint_as_float(f2tf(t.x));
    s.y = __uint_as_float(f2tf(t.y));
    s.z = __uint_as_float(f2tf(t.z));
    s.w = __uint_as_float(f2tf(t.w));
    *(float4*)(g_wc + (size_t)w * DIM * DIM + j) = s;
}

// ---------------- fused GEMM (tf32 mma.sync, cp.async 4-stage pipeline) ----
#define BM 128
#define BN 64
#define BK 16
#define STAGES 4
#define A_STAGE 2048                  // floats: 128 x 16, XOR-swizzled
#define B_STAGE 3456                  // floats: 3 x 16 x 72 (pad 8)
#define STAGE_F (A_STAGE + B_STAGE)   // 5504 floats = 22016 B
#define NITER (DIM/BK)                // 32
#define GEMM_SMEM (STAGES*STAGE_F*4)  // 88064 B

__global__ __launch_bounds__(256) void gemm_act(
    const float* __restrict__ x,
    const float* __restrict__ bfp, const float* __restrict__ bip,
    const float* __restrict__ bhp)
{
    extern __shared__ float sm[];
    const unsigned smBase = (unsigned)__cvta_generic_to_shared(sm);

    const int tid  = threadIdx.x;
    const int lane = tid & 31;
    const int wid  = tid >> 5;
    const int wm   = wid >> 1;   // 0..3
    const int wn   = wid & 1;    // 0..1
    const int m0   = blockIdx.x * BM;
    const int n0   = blockIdx.y * BN;

    float acc[3][2][4][4];
    #pragma unroll
    for (int w = 0; w < 3; w++)
        #pragma unroll
        for (int mf = 0; mf < 2; mf++)
            #pragma unroll
            for (int nf = 0; nf < 4; nf++)
                #pragma unroll
                for (int r = 0; r < 4; r++)
                    acc[w][mf][nf][r] = 0.0f;

    auto issue = [&](int buf, int k0) {
        unsigned sb = smBase + buf * (STAGE_F * 4);
        // A: 512 16B-chunks, 2 per thread, XOR-swizzled (chunk ^= (r>>1)&3)
        #pragma unroll
        for (int it = 0; it < 2; it++) {
            int j  = tid + it * 256;
            int r  = j >> 2;
            int cv = j & 3;
            int pc = cv ^ ((r >> 1) & 3);
            cpasync16(sb + (unsigned)(r * 16 + pc * 4) * 4,
                      x + (size_t)(m0 + r) * DIM + k0 + cv * 4);
        }
        // B: 3 x 256 16B-chunks, 3 per thread, row pad 8 floats
        #pragma unroll
        for (int t = 0; t < 3; t++) {
            int cj  = tid + t * 256;
            int w   = cj >> 8;
            int idx = cj & 255;
            int kr  = idx >> 4;
            int cv  = idx & 15;
            cpasync16(sb + (unsigned)(A_STAGE + w * 1152 + kr * 72 + cv * 4) * 4,
                      g_wc + (size_t)w * DIM * DIM + (size_t)(k0 + kr) * DIM + n0 + cv * 4);
        }
        asm volatile("cp.async.commit_group;");
    };

    #pragma unroll
    for (int s = 0; s < STAGES - 1; s++) issue(s, s * BK);

    const int q = lane & 3;
    const int p = lane >> 2;

    for (int i = 0; i < NITER; i++) {
        asm volatile("cp.async.wait_group %0;" :: "n"(STAGES - 2));
        __syncthreads();
        int nk = i + STAGES - 1;
        if (nk < NITER) issue(nk & (STAGES - 1), nk * BK);
        else            asm volatile("cp.async.commit_group;");

        const float* As = sm + (i & (STAGES - 1)) * STAGE_F;
        const float* Bs = As + A_STAGE;

        #pragma unroll
        for (int kk = 0; kk < BK; kk += 8) {
            const int c0 = kk >> 2;       // chunk of col kk+q
            const int c1 = c0 + 1;        // chunk of col kk+q+4
            unsigned a[2][4];
            #pragma unroll
            for (int mf = 0; mf < 2; mf++) {
                int r  = wm * 32 + mf * 16 + p;
                int r8 = r + 8;
                int sr  = (r  >> 1) & 3;
                int sr8 = (r8 >> 1) & 3;
                a[mf][0] = f2tf(As[r  * 16 + (c0 ^ sr ) * 4 + q]);
                a[mf][1] = f2tf(As[r8 * 16 + (c0 ^ sr8) * 4 + q]);
                a[mf][2] = f2tf(As[r  * 16 + (c1 ^ sr ) * 4 + q]);
                a[mf][3] = f2tf(As[r8 * 16 + (c1 ^ sr8) * 4 + q]);
            }
            #pragma unroll
            for (int w = 0; w < 3; w++) {
                #pragma unroll
                for (int nf = 0; nf < 4; nf++) {
                    int cn = wn * 32 + nf * 8 + p;
                    unsigned b0 = __float_as_uint(Bs[w * 1152 + (kk + q)     * 72 + cn]);
                    unsigned b1 = __float_as_uint(Bs[w * 1152 + (kk + 4 + q) * 72 + cn]);
                    #pragma unroll
                    for (int mf = 0; mf < 2; mf++) {
                        float* c = acc[w][mf][nf];
                        asm volatile(
                            "mma.sync.aligned.m16n8k8.row.col.f32.tf32.tf32.f32 "
                            "{%0,%1,%2,%3}, {%4,%5,%6,%7}, {%8,%9}, {%0,%1,%2,%3};"
                            : "+f"(c[0]), "+f"(c[1]), "+f"(c[2]), "+f"(c[3])
                            : "r"(a[mf][0]), "r"(a[mf][1]), "r"(a[mf][2]), "r"(a[mf][3]),
                              "r"(b0), "r"(b1));
                    }
                }
            }
        }
    }

    // ---- epilogue: activations, write f and v as fp16 ----
    #pragma unroll
    for (int mf = 0; mf < 2; mf++) {
        #pragma unroll
        for (int nf = 0; nf < 4; nf++) {
            int gm0 = m0 + wm * 32 + mf * 16 + p;
            int gn  = n0 + wn * 32 + nf * 8 + 2 * q;
            float bf0 = bfp[gn], bf1 = bfp[gn + 1];
            float bi0 = bip[gn], bi1 = bip[gn + 1];
            float bh0 = bhp[gn], bh1 = bhp[gn + 1];
            #pragma unroll
            for (int half = 0; half < 2; half++) {
                int gm = gm0 + half * 8;
                float yf0 = acc[0][mf][nf][half * 2 + 0] + bf0;
                float yf1 = acc[0][mf][nf][half * 2 + 1] + bf1;
                float yi0 = acc[1][mf][nf][half * 2 + 0] + bi0;
                float yi1 = acc[1][mf][nf][half * 2 + 1] + bi1;
                float yh0 = acc[2][mf][nf][half * 2 + 0] + bh0;
                float yh1 = acc[2][mf][nf][half * 2 + 1] + bh1;

                float f0 = sigmoidf_(yf0);
                float f1 = sigmoidf_(yf1);
                float gg0 = (yh0 >= 0.0f) ? (yh0 + 0.5f) : sigmoidf_(yh0);
                float gg1 = (yh1 >= 0.0f) ? (yh1 + 0.5f) : sigmoidf_(yh1);
                float v0 = sigmoidf_(yi0) * gg0;
                float v1 = sigmoidf_(yi1) * gg1;

                *(__half2*)&g_f16[(size_t)gm * DIM + gn] = __floats2half2_rn(f0, f1);
                *(__half2*)&g_v16[(size_t)gm * DIM + gn] = __floats2half2_rn(v0, v1);
            }
        }
    }
}

// ---------------- scan phase 1: per-chunk reduction ------------------------
__global__ __launch_bounds__(256) void chunk_reduce()
{
    int c  = blockIdx.x;          // chunk 0..63
    int b  = blockIdx.y;          // batch
    int d2 = threadIdx.x;         // channel pair 0..255
    size_t base = ((size_t)(b * SEQ + c * CHUNK)) * DIM + 2 * d2;
    float2 P = make_float2(1.0f, 1.0f);
    float2 V = make_float2(0.0f, 0.0f);
    #pragma unroll 8
    for (int t = 0; t < CHUNK; t++) {
        float2 f = __half22float2(*(const __half2*)(g_f16 + base + (size_t)t * DIM));
        float2 v = __half22float2(*(const __half2*)(g_v16 + base + (size_t)t * DIM));
        V.x = fmaf(f.x, V.x, v.x);  V.y = fmaf(f.y, V.y, v.y);
        P.x *= f.x;                 P.y *= f.y;
    }
    int ch = b * DIM + 2 * d2;
    g_P[(size_t)ch * NCHUNK + c]       = P.x;
    g_P[(size_t)(ch + 1) * NCHUNK + c] = P.y;
    g_V[(size_t)ch * NCHUNK + c]       = V.x;
    g_V[(size_t)(ch + 1) * NCHUNK + c] = V.y;
}

// ---------------- scan phase 2: sequential carry scan over chunks ----------
__global__ void carry_scan(const float* __restrict__ pre_h)
{
    int ch = blockIdx.x * blockDim.x + threadIdx.x;   // 0..2047
    if (ch >= BATCH * DIM) return;
    float pv = pre_h[ch];
    float h = (pv >= 0.0f) ? (pv + 0.5f) : sigmoidf_(pv);   // g(pre_h)
    #pragma unroll
    for (int c = 0; c < NCHUNK; c++) {
        g_hin[(size_t)ch * NCHUNK + c] = h;
        h = fmaf(g_P[(size_t)ch * NCHUNK + c], h, g_V[(size_t)ch * NCHUNK + c]);
    }
}

// ---------------- scan phase 3: apply with true carry-in, write output -----
__global__ __launch_bounds__(256) void chunk_apply(float* __restrict__ out)
{
    int c  = blockIdx.x;
    int b  = blockIdx.y;
    int d2 = threadIdx.x;
    int ch = b * DIM + 2 * d2;
    float2 h;
    h.x = g_hin[(size_t)ch * NCHUNK + c];
    h.y = g_hin[(size_t)(ch + 1) * NCHUNK + c];
    size_t base = ((size_t)(b * SEQ + c * CHUNK)) * DIM + 2 * d2;
    #pragma unroll 8
    for (int t = 0; t < CHUNK; t++) {
        float2 f = __half22float2(*(const __half2*)(g_f16 + base + (size_t)t * DIM));
        float2 v = __half22float2(*(const __half2*)(g_v16 + base + (size_t)t * DIM));
        h.x = fmaf(f.x, h.x, v.x);
        h.y = fmaf(f.y, h.y, v.y);
        *(float2*)(out + base + (size_t)t * DIM) = h;
    }
}

// ---------------- launch ----------------------------------------------------
extern "C" void kernel_launch(void* const* d_in, const int* in_sizes, int n_in,
                              void* d_out, int out_size)
{
    const float* x     = (const float*)d_in[0];
    const float* pre_h = (const float*)d_in[1];
    const float* Wf    = (const float*)d_in[2];
    const float* bf    = (const float*)d_in[3];
    const float* Wi    = (const float*)d_in[4];
    const float* bi    = (const float*)d_in[5];
    const float* Wh    = (const float*)d_in[6];
    const float* bh    = (const float*)d_in[7];
    float* out = (float*)d_out;

    cudaFuncSetAttribute(gemm_act, cudaFuncAttributeMaxDynamicSharedMemorySize, GEMM_SMEM);

    wconv<<<768, 256>>>(Wf, Wi, Wh);
    dim3 g1(M_TOTAL / BM, DIM / BN);      // 256 x 8
    gemm_act<<<g1, 256, GEMM_SMEM>>>(x, bf, bi, bh);
    chunk_reduce<<<dim3(NCHUNK, BATCH), 256>>>();
    carry_scan<<<8, 256>>>(pre_h);
    chunk_apply<<<dim3(NCHUNK, BATCH), 256>>>(out);
}

// round 5
// speedup vs baseline: 2.3176x; 1.9949x over previous
#include <cuda_runtime.h>
#include <cuda_fp16.h>

#define BATCH 4
#define SEQ   8192
#define DIM   512
#define M_TOTAL (BATCH*SEQ)   // 32768

#define NCHUNK 64
#define CHUNK  128            // == TILE_M

#define TILE_M 128
#define TILE_N 64
#define BK     32
#define NSTG   (DIM/BK)       // 16
#define STAGES 4

#define A_PITCH_B 80                     // bytes per A row (32 halfs + 8 pad)
#define A_BYTES   (TILE_M*A_PITCH_B)     // 10240
#define B_PITCH_B 144                    // bytes per B k-row (64 halfs + 8 pad)
#define B_GATE    (BK*B_PITCH_B)         // 4608
#define B_BYTES   (3*B_GATE)             // 13824
#define STG_BYTES (A_BYTES+B_BYTES)      // 24064
#define DYN_SMEM  (1024 + STAGES*STG_BYTES)

// ---------------- scratch ---------------------------------------------------
__device__ __half  g_x16[(size_t)M_TOTAL*DIM];   // x in fp16, 32MB
__device__ __half  g_w16[3*DIM*DIM];             // W fp16, [w][k][n], 1.5MB
__device__ __half2 g_fv[(size_t)M_TOTAL*DIM];    // (f,v) packed, 64MB
__device__ float   g_P[NCHUNK*BATCH*DIM];
__device__ float   g_V[NCHUNK*BATCH*DIM];
__device__ float   g_hin[NCHUNK*BATCH*DIM];

__device__ __forceinline__ float sigmoidf_(float x) { return 1.0f / (1.0f + __expf(-x)); }
__device__ __forceinline__ unsigned smem_u32(const void* p) {
    unsigned a;
    asm("{ .reg .u64 t; cvta.to.shared.u64 t, %1; cvt.u32.u64 %0, t; }" : "=r"(a) : "l"(p));
    return a;
}
__device__ __forceinline__ void cpasync16(unsigned dst, const void* src) {
    asm volatile("cp.async.cg.shared.global [%0], [%1], 16;" :: "r"(dst), "l"(src));
}
__device__ __forceinline__ void ldsm4(unsigned* r, unsigned addr) {
    asm volatile("ldmatrix.sync.aligned.m8n8.x4.shared.b16 {%0,%1,%2,%3}, [%4];"
                 : "=r"(r[0]), "=r"(r[1]), "=r"(r[2]), "=r"(r[3]) : "r"(addr));
}
__device__ __forceinline__ void ldsm4t(unsigned* r, unsigned addr) {
    asm volatile("ldmatrix.sync.aligned.m8n8.x4.trans.shared.b16 {%0,%1,%2,%3}, [%4];"
                 : "=r"(r[0]), "=r"(r[1]), "=r"(r[2]), "=r"(r[3]) : "r"(addr));
}
__device__ __forceinline__ void mma16816(float* c, const unsigned* a, unsigned b0, unsigned b1) {
    asm volatile("mma.sync.aligned.m16n8k16.row.col.f32.f16.f16.f32 "
                 "{%0,%1,%2,%3}, {%4,%5,%6,%7}, {%8,%9}, {%0,%1,%2,%3};"
                 : "+f"(c[0]), "+f"(c[1]), "+f"(c[2]), "+f"(c[3])
                 : "r"(a[0]), "r"(a[1]), "r"(a[2]), "r"(a[3]), "r"(b0), "r"(b1));
}

// ---------------- prepass: x -> fp16 ----------------------------------------
__global__ __launch_bounds__(256) void xconv(const float* __restrict__ x)
{
    size_t i = ((size_t)blockIdx.x * 256 + threadIdx.x) * 4;
    float4 t = *(const float4*)(x + i);
    __half2 lo = __floats2half2_rn(t.x, t.y);
    __half2 hi = __floats2half2_rn(t.z, t.w);
    *(__half2*)(g_x16 + i)     = lo;
    *(__half2*)(g_x16 + i + 2) = hi;
}

// ---------------- prepass: W -> fp16 (layout preserved [k][n]) ---------------
__global__ __launch_bounds__(256) void wconv(
    const float* __restrict__ Wf, const float* __restrict__ Wi,
    const float* __restrict__ Wh)
{
    size_t j = ((size_t)blockIdx.x * 256 + threadIdx.x) * 4;
    int w = (int)(j >> 18);
    size_t off = j & (DIM*DIM - 1);
    const float* W = (w == 0) ? Wf : (w == 1) ? Wi : Wh;
    float4 t = *(const float4*)(W + off);
    *(__half2*)(g_w16 + (size_t)w * DIM * DIM + off)     = __floats2half2_rn(t.x, t.y);
    *(__half2*)(g_w16 + (size_t)w * DIM * DIM + off + 2) = __floats2half2_rn(t.z, t.w);
}

// ---------------- fp16 mma.sync GEMM + activations + fused chunk reduce -----
__global__ __launch_bounds__(256) void gemm_act(
    const float* __restrict__ bfp, const float* __restrict__ bip,
    const float* __restrict__ bhp)
{
    extern __shared__ char dsm[];
    __shared__ float s_bias[3*TILE_N];

    const int tid  = threadIdx.x;
    const int wid  = tid >> 5;
    const int lane = tid & 31;
    const int wm   = wid >> 1;   // 0..3
    const int wn   = wid & 1;    // 0..1
    const int n0   = blockIdx.x * TILE_N;
    const int m0   = blockIdx.y * TILE_M;

    unsigned raw = smem_u32(dsm);
    unsigned sma = (raw + 1023u) & ~1023u;

    if (tid < 3*TILE_N) {
        int w = tid >> 6, c = tid & 63;
        const float* b = (w == 0) ? bfp : (w == 1) ? bip : bhp;
        s_bias[tid] = b[n0 + c];
    }

    float acc[3][2][4][4];
    #pragma unroll
    for (int g = 0; g < 3; g++)
        #pragma unroll
        for (int mi = 0; mi < 2; mi++)
            #pragma unroll
            for (int ni = 0; ni < 4; ni++)
                #pragma unroll
                for (int r = 0; r < 4; r++)
                    acc[g][mi][ni][r] = 0.0f;

    auto fill = [&](int buf, int k0e) {
        unsigned sb = sma + buf * STG_BYTES;
        // A: 128 rows x 4 chunks = 512 cp.async (16B each)
        #pragma unroll
        for (int i = 0; i < 2; i++) {
            int c = tid + 256 * i;
            int r = c >> 2, q = c & 3;
            cpasync16(sb + (unsigned)(r * A_PITCH_B + q * 16),
                      g_x16 + (size_t)(m0 + r) * DIM + k0e + q * 8);
        }
        // B: 3 gates x 32 k-rows x 8 chunks = 768 cp.async
        #pragma unroll
        for (int i = 0; i < 3; i++) {
            int c = tid + 256 * i;
            int g = c >> 8, rq = c & 255;
            int k = rq >> 3, q = rq & 7;
            cpasync16(sb + (unsigned)(A_BYTES + g * B_GATE + k * B_PITCH_B + q * 16),
                      g_w16 + (size_t)g * DIM * DIM + (size_t)(k0e + k) * DIM + n0 + q * 8);
        }
        asm volatile("cp.async.commit_group;");
    };

    #pragma unroll
    for (int s = 0; s < STAGES - 1; s++) fill(s, s * BK);

    const int l15 = lane & 15;
    const int l16 = lane >> 4;

    for (int i = 0; i < NSTG; i++) {
        asm volatile("cp.async.wait_group %0;" :: "n"(STAGES - 2));
        __syncthreads();
        int j = i + STAGES - 1;
        if (j < NSTG) fill(j & (STAGES - 1), j * BK);
        else          asm volatile("cp.async.commit_group;");

        unsigned sb = sma + (i & (STAGES - 1)) * STG_BYTES;

        #pragma unroll
        for (int kk = 0; kk < BK; kk += 16) {
            unsigned a[2][4];
            #pragma unroll
            for (int mi = 0; mi < 2; mi++) {
                unsigned addr = sb + (unsigned)((wm * 32 + mi * 16 + l15) * A_PITCH_B
                                                + (kk + l16 * 8) * 2);
                ldsm4(a[mi], addr);
            }
            #pragma unroll
            for (int g = 0; g < 3; g++) {
                unsigned b[2][4];
                #pragma unroll
                for (int nh = 0; nh < 2; nh++) {
                    unsigned addr = sb + (unsigned)(A_BYTES + g * B_GATE
                                                    + (kk + l15) * B_PITCH_B
                                                    + (wn * 32 + nh * 16 + l16 * 8) * 2);
                    ldsm4t(b[nh], addr);
                }
                #pragma unroll
                for (int ni = 0; ni < 4; ni++) {
                    unsigned b0 = b[ni >> 1][(ni & 1) * 2];
                    unsigned b1 = b[ni >> 1][(ni & 1) * 2 + 1];
                    #pragma unroll
                    for (int mi = 0; mi < 2; mi++)
                        mma16816(acc[g][mi][ni], a[mi], b0, b1);
                }
            }
        }
    }

    // ---- epilogue: activations -> smem staging (half2 f,v) ----
    __half2* sfv = (__half2*)(dsm + (sma - raw));
    const int PITCH = 65;   // half2 units per m-row

    #pragma unroll
    for (int mi = 0; mi < 2; mi++) {
        #pragma unroll
        for (int ni = 0; ni < 4; ni++) {
            int lm = wm * 32 + mi * 16 + (lane >> 2);
            int ln = wn * 32 + ni * 8 + 2 * (lane & 3);
            #pragma unroll
            for (int half = 0; half < 2; half++) {
                int m = lm + half * 8;
                #pragma unroll
                for (int e = 0; e < 2; e++) {
                    int c = ln + e;
                    float yf = acc[0][mi][ni][half * 2 + e] + s_bias[c];
                    float yi = acc[1][mi][ni][half * 2 + e] + s_bias[TILE_N + c];
                    float yh = acc[2][mi][ni][half * 2 + e] + s_bias[2*TILE_N + c];
                    float f  = sigmoidf_(yf);
                    float gg = (yh >= 0.0f) ? (yh + 0.5f) : sigmoidf_(yh);
                    float v  = sigmoidf_(yi) * gg;
                    sfv[m * PITCH + c] = __floats2half2_rn(f, v);
                }
            }
        }
    }
    __syncthreads();

    // ---- fused chunk reduction over 128 timesteps (4 segments of 32) ----
    {
        int c = tid >> 2;         // channel 0..63
        int q = tid & 3;          // segment
        float P = 1.0f, V = 0.0f;
        #pragma unroll 8
        for (int s = 0; s < 32; s++) {
            float2 fv = __half22float2(sfv[(q * 32 + s) * PITCH + c]);
            V = fmaf(fv.x, V, fv.y);
            P *= fv.x;
        }
        #pragma unroll
        for (int msk = 1; msk <= 2; msk <<= 1) {
            float Po = __shfl_xor_sync(0xffffffff, P, msk);
            float Vo = __shfl_xor_sync(0xffffffff, V, msk);
            if ((q & msk) == 0) V = fmaf(Po, V, Vo);   // I'm the earlier segment
            else                V = fmaf(P, Vo, V);    // I'm the later segment
            P *= Po;
        }
        if (q == 0) {
            int bb = m0 / SEQ;
            int ck = (m0 % SEQ) / CHUNK;
            size_t idx = (size_t)ck * (BATCH*DIM) + bb * DIM + n0 + c;
            g_P[idx] = P;
            g_V[idx] = V;
        }
    }

    // ---- store staging tile to global (coalesced) ----
    #pragma unroll 8
    for (int t = 0; t < 32; t++) {
        int idx = tid + 256 * t;
        int m = idx >> 6, c = idx & 63;
        g_fv[(size_t)(m0 + m) * DIM + n0 + c] = sfv[m * PITCH + c];
    }
}

// ---------------- carry scan over chunks (coalesced, MLP-batched) ----------
__global__ __launch_bounds__(256) void carry_scan(const float* __restrict__ pre_h)
{
    int ch = blockIdx.x * 256 + threadIdx.x;   // 0..2047
    float P[NCHUNK], V[NCHUNK];
    #pragma unroll
    for (int c = 0; c < NCHUNK; c++) P[c] = g_P[(size_t)c * (BATCH*DIM) + ch];
    #pragma unroll
    for (int c = 0; c < NCHUNK; c++) V[c] = g_V[(size_t)c * (BATCH*DIM) + ch];
    float pv = pre_h[ch];
    float h = (pv >= 0.0f) ? (pv + 0.5f) : sigmoidf_(pv);
    #pragma unroll
    for (int c = 0; c < NCHUNK; c++) {
        g_hin[(size_t)c * (BATCH*DIM) + ch] = h;
        h = fmaf(P[c], h, V[c]);
    }
}

// ---------------- apply: h = f*h + v, write output --------------------------
__global__ __launch_bounds__(512) void chunk_apply(float* __restrict__ out)
{
    int ck = blockIdx.x;
    int b  = blockIdx.y;
    int n  = threadIdx.x;
    float h = g_hin[(size_t)ck * (BATCH*DIM) + b * DIM + n];
    size_t base = ((size_t)(b * SEQ + ck * CHUNK)) * DIM + n;
    #pragma unroll 8
    for (int t = 0; t < CHUNK; t++) {
        float2 fv = __half22float2(g_fv[base + (size_t)t * DIM]);
        h = fmaf(fv.x, h, fv.y);
        out[base + (size_t)t * DIM] = h;
    }
}

// ---------------- launch ----------------------------------------------------
extern "C" void kernel_launch(void* const* d_in, const int* in_sizes, int n_in,
                              void* d_out, int out_size)
{
    const float* x     = (const float*)d_in[0];
    const float* pre_h = (const float*)d_in[1];
    const float* Wf    = (const float*)d_in[2];
    const float* bf    = (const float*)d_in[3];
    const float* Wi    = (const float*)d_in[4];
    const float* bi    = (const float*)d_in[5];
    const float* Wh    = (const float*)d_in[6];
    const float* bh    = (const float*)d_in[7];
    float* out = (float*)d_out;

    cudaFuncSetAttribute(gemm_act, cudaFuncAttributeMaxDynamicSharedMemorySize, DYN_SMEM);

    xconv<<<M_TOTAL*DIM/1024, 256>>>(x);
    wconv<<<3*DIM*DIM/1024, 256>>>(Wf, Wi, Wh);
    gemm_act<<<dim3(DIM / TILE_N, M_TOTAL / TILE_M), 256, DYN_SMEM>>>(bf, bi, bh);
    carry_scan<<<8, 256>>>(pre_h);
    chunk_apply<<<dim3(NCHUNK, BATCH), 512>>>(out);
}